// round 13
// baseline (speedup 1.0000x reference)
#include <cuda_runtime.h>
#include <cuda_bf16.h>
#include <math.h>
#include <stdint.h>

#define Bsz 256
#define Tt  32
#define Ssz 2048
#define Asz 64
#define Psz 128
#define KAP 192
#define SAP 2240
#define S4  8192
#define K3S 6144          // 3*Ssz
#define K3P 576           // 3*KAP

// ---- scratch (device globals; allocation-free rule) ----
__device__ __nv_bfloat16 g_eff3 [(size_t)Ssz * K3S];
__device__ __nv_bfloat16 g_fc23 [(size_t)Ssz * K3S];
__device__ __nv_bfloat16 g_WW3  [(size_t)S4  * K3S];
__device__ __nv_bfloat16 g_fcs3 [(size_t)Ssz * K3S];
__device__ __nv_bfloat16 g_fcap3[(size_t)Ssz * K3P];
__device__ __nv_bfloat16 g_al3  [(size_t)Tt * Bsz * K3P];
__device__ __nv_bfloat16 g_st3  [(size_t)Bsz * K3S];
__device__ __nv_bfloat16 g_h3   [(size_t)Bsz * K3S];
__device__ __nv_bfloat16 g_x13  [(size_t)Bsz * K3S];
__device__ __nv_bfloat16 g_x23  [(size_t)Bsz * K3S];
__device__ __nv_bfloat16 g_hn3  [(size_t)Bsz * K3S];
__device__ float g_base[(size_t)Tt * Bsz * Ssz];
__device__ float g_cc  [(size_t)Bsz * S4];
__device__ float g_c   [(size_t)Bsz * Ssz];

__device__ __forceinline__ uint32_t smem_u32(const void* p) {
    uint32_t a;
    asm("{ .reg .u64 t; cvta.to.shared.u64 t, %1; cvt.u32.u64 %0, t; }" : "=r"(a) : "l"(p));
    return a;
}
__device__ __forceinline__ void ldmx4(uint32_t* r, uint32_t addr) {
    asm volatile("ldmatrix.sync.aligned.m8n8.x4.shared.b16 {%0,%1,%2,%3}, [%4];"
                 : "=r"(r[0]), "=r"(r[1]), "=r"(r[2]), "=r"(r[3]) : "r"(addr));
}
__device__ __forceinline__ void mma16816(float* c, const uint32_t* a, uint32_t b0, uint32_t b1) {
    asm volatile(
        "mma.sync.aligned.m16n8k16.row.col.f32.bf16.bf16.f32 "
        "{%0,%1,%2,%3}, {%4,%5,%6,%7}, {%8,%9}, {%0,%1,%2,%3};"
        : "+f"(c[0]), "+f"(c[1]), "+f"(c[2]), "+f"(c[3])
        : "r"(a[0]), "r"(a[1]), "r"(a[2]), "r"(a[3]), "r"(b0), "r"(b1));
}

// ---------------------------------------------------------------------------
// Warp-mma bf16 GEMM: D[m,n] = epi( sum_{k<K3} A3[m,k]*W3[n,k] ), fp32 acc.
// Tiles: CTA 128x32, BK=64 bf16; 8 warps (4 in M x 2 in N), warp tile 32x16.
// MODE 0: relu -> O3 (bf16 hi|hi|lo rows, length 3*Kout)
// MODE 1: relu(acc + extra[m*Nfull+n]) -> O3 (+ optional fp32 dup to Cf)
// MODE 2: relu -> Cf fp32      MODE 3: acc + extra[n] -> Cf fp32 (no relu)
// ---------------------------------------------------------------------------
template <int MODE>
__global__ __launch_bounds__(256) void mmagemm(
    const __nv_bfloat16* __restrict__ A3, int K3,
    const __nv_bfloat16* __restrict__ W3,
    float* __restrict__ Cf,
    __nv_bfloat16* __restrict__ O3,
    const float* __restrict__ extra,
    int Nfull, int Kout)
{
    __shared__ __nv_bfloat16 As[2][128 * 64];   // 16KB per buf, 128B rows, XOR swizzle
    __shared__ __nv_bfloat16 Ws[2][32 * 64];    // 4KB per buf

    const int tid = threadIdx.x;
    const int wid = tid >> 5;
    const int l   = tid & 31;
    const int bm  = blockIdx.y * 128;
    const int n0  = blockIdx.x * 32;
    const int NS  = K3 >> 6;

    const int wm = wid >> 1;            // 0..3 -> M offset 32*wm
    const int wn = wid & 1;             // 0..1 -> N offset 16*wn
    const int mr = wm * 32;
    const int nb = wn * 16;

    const uint32_t sA = smem_u32(&As[0][0]);
    const uint32_t sW = smem_u32(&Ws[0][0]);

    // ---- global->smem loader mapping ----
    const int arow = tid >> 1, ah = tid & 1;        // A: 2 thr/row, 64B each
    const int wrow = tid >> 3, wc = tid & 7;        // W: 8 thr/row, 16B each
    const __nv_bfloat16* gA = A3 + (size_t)(bm + arow) * K3 + ah * 32;
    const __nv_bfloat16* gW = W3 + (size_t)(n0 + wrow) * K3 + wc * 8;
    uint32_t sa[4], swo;
    {
#pragma unroll
        for (int i = 0; i < 4; i++) {
            uint32_t o = (uint32_t)(arow * 128 + ah * 64 + i * 16);
            sa[i] = o ^ ((o >> 3) & 0x70);
        }
        uint32_t o = (uint32_t)(wrow * 128 + wc * 16);
        swo = o ^ ((o >> 3) & 0x70);
    }

    // ---- ldmatrix per-thread base offsets ----
    const int rowA = mr + (l & 15);
    const uint32_t baseA = (uint32_t)(rowA * 128 + ((l >> 4) << 4));
    const int rowW = nb + (((l >> 4) & 1) << 3) + (l & 7);
    const uint32_t baseW = (uint32_t)(rowW * 128 + (((l >> 3) & 1) << 4));
    const uint32_t xr = (uint32_t)((l & 7) << 4);   // row-dependent XOR (bits 4-6)

    float acc[2][2][4] = {};

    // prologue: stage 0 -> buf 0
    float4 av[4], wv;
#pragma unroll
    for (int i = 0; i < 4; i++) av[i] = *(const float4*)(gA + i * 8);
    wv = *(const float4*)(gW);
#pragma unroll
    for (int i = 0; i < 4; i++) *(float4*)((char*)As[0] + sa[i]) = av[i];
    *(float4*)((char*)Ws[0] + swo) = wv;
    __syncthreads();

    for (int c = 0; c < NS; c++) {
        const int buf = c & 1;
        if (c + 1 < NS) {
            const __nv_bfloat16* pA = gA + (size_t)(c + 1) * 64;
            const __nv_bfloat16* pW = gW + (size_t)(c + 1) * 64;
#pragma unroll
            for (int i = 0; i < 4; i++) av[i] = *(const float4*)(pA + i * 8);
            wv = *(const float4*)(pW);
        }
        const uint32_t sAb = sA + buf * 16384;
        const uint32_t sWb = sW + buf * 4096;
#pragma unroll
        for (int s = 0; s < 4; s++) {
            uint32_t a0[4], a1[4], b[4];
            ldmx4(a0, sAb + ((baseA + s * 32) ^ xr));            // m16 group 0
            ldmx4(a1, sAb + ((baseA + 2048 + s * 32) ^ xr));     // m16 group 1
            ldmx4(b,  sWb + ((baseW + s * 32) ^ xr));            // n8 groups 0,1
            mma16816(acc[0][0], a0, b[0], b[1]);
            mma16816(acc[0][1], a0, b[2], b[3]);
            mma16816(acc[1][0], a1, b[0], b[1]);
            mma16816(acc[1][1], a1, b[2], b[3]);
        }
        if (c + 1 < NS) {
            const int nbuf = buf ^ 1;
#pragma unroll
            for (int i = 0; i < 4; i++) *(float4*)((char*)As[nbuf] + sa[i]) = av[i];
            *(float4*)((char*)Ws[nbuf] + swo) = wv;
        }
        __syncthreads();
    }

    // ---- epilogue: thread owns pairs (m, n..n+1) ----
#pragma unroll
    for (int g = 0; g < 2; g++) {
#pragma unroll
        for (int j = 0; j < 2; j++) {
            const int n = n0 + nb + j * 8 + (l & 3) * 2;
#pragma unroll
            for (int half = 0; half < 2; half++) {
                const int m = bm + mr + g * 16 + (l >> 2) + half * 8;
                float v0 = acc[g][j][half * 2 + 0];
                float v1 = acc[g][j][half * 2 + 1];
                if (MODE == 1) {
                    const float2 e = *(const float2*)(extra + (size_t)m * Nfull + n);
                    v0 += e.x; v1 += e.y;
                }
                if (MODE == 3) { v0 += extra[n]; v1 += extra[n + 1]; }
                if (MODE != 3) {
                    v0 = v0 > 0.f ? v0 : 0.f;
                    v1 = v1 > 0.f ? v1 : 0.f;
                }
                if (MODE >= 2 || (MODE == 1 && Cf != nullptr))
                    *(float2*)(Cf + (size_t)m * Nfull + n) = make_float2(v0, v1);
                if (MODE <= 1) {
                    __nv_bfloat16 h0 = __float2bfloat16_rn(v0);
                    __nv_bfloat16 h1 = __float2bfloat16_rn(v1);
                    __nv_bfloat16 l0 = __float2bfloat16_rn(v0 - __bfloat162float(h0));
                    __nv_bfloat16 l1 = __float2bfloat16_rn(v1 - __bfloat162float(h1));
                    uint32_t ph = ((uint32_t)__bfloat16_as_ushort(h1) << 16) | __bfloat16_as_ushort(h0);
                    uint32_t pl = ((uint32_t)__bfloat16_as_ushort(l1) << 16) | __bfloat16_as_ushort(l0);
                    __nv_bfloat16* ob = O3 + (size_t)m * (3 * Kout) + n;
                    *(uint32_t*)(ob)            = ph;
                    *(uint32_t*)(ob + Kout)     = ph;
                    *(uint32_t*)(ob + 2 * Kout) = pl;
                }
            }
        }
    }
}

// ---- conversions ----
__device__ __forceinline__ void split_bf(float v, __nv_bfloat16& h, __nv_bfloat16& l) {
    h = __float2bfloat16_rn(v);
    l = __float2bfloat16_rn(v - __bfloat162float(h));
}
// W order [hi|lo|hi]
__global__ void convw_k(const float* __restrict__ src, int ld, int coloff, int K,
                        __nv_bfloat16* __restrict__ dst, long total)
{
    long idx = (long)blockIdx.x * blockDim.x + threadIdx.x;
    if (idx >= total) return;
    int k = (int)(idx % K); long n = idx / K;
    __nv_bfloat16 h, l; split_bf(src[(size_t)n * ld + coloff + k], h, l);
    size_t b = (size_t)n * 3 * K;
    dst[b + k] = h; dst[b + K + k] = l; dst[b + 2*K + k] = h;
}
// A order [hi|hi|lo]
__global__ void conva_k(const float* __restrict__ src, int ld, int K,
                        __nv_bfloat16* __restrict__ dst, long total)
{
    long idx = (long)blockIdx.x * blockDim.x + threadIdx.x;
    if (idx >= total) return;
    int k = (int)(idx % K); long n = idx / K;
    __nv_bfloat16 h, l; split_bf(src[(size_t)n * ld + k], h, l);
    size_t b = (size_t)n * 3 * K;
    dst[b + k] = h; dst[b + K + k] = h; dst[b + 2*K + k] = l;
}
// folded fc1 (combined=[h,h]) in W order
__global__ void conveff_k(const float* __restrict__ w1, __nv_bfloat16* __restrict__ dst)
{
    long idx = (long)blockIdx.x * blockDim.x + threadIdx.x;
    if (idx >= (long)Ssz * Ssz) return;
    int k = (int)(idx % Ssz); long n = idx / Ssz;
    __nv_bfloat16 h, l;
    split_bf(w1[(size_t)n * 2*Ssz + k] + w1[(size_t)n * 2*Ssz + Ssz + k], h, l);
    size_t b = (size_t)n * K3S;
    dst[b + k] = h; dst[b + Ssz + k] = l; dst[b + 2*Ssz + k] = h;
}
// packed [act_t, latent] rows in A order, K=KAP
__global__ void packal_k(const float* __restrict__ act, const float* __restrict__ lat,
                         __nv_bfloat16* __restrict__ dst)
{
    long idx = (long)blockIdx.x * blockDim.x + threadIdx.x;
    if (idx >= (long)Tt * Bsz * KAP) return;
    int k = (int)(idx % KAP); long r = idx / KAP;
    int b = (int)(r % Bsz), t = (int)(r / Bsz);
    float v = (k < Asz) ? act[((size_t)b * Tt + t) * Asz + k]
                        : lat[(size_t)b * Psz + (k - Asz)];
    __nv_bfloat16 h, l; split_bf(v, h, l);
    size_t o = (size_t)r * K3P;
    dst[o + k] = h; dst[o + KAP + k] = h; dst[o + 2*KAP + k] = l;
}

// LSTM gates; emits hn in A-order bf16 split for the carry GEMM.
__global__ __launch_bounds__(256) void gates_k(
    const float* __restrict__ cc, float* __restrict__ c,
    __nv_bfloat16* __restrict__ hn3, float* __restrict__ preds,
    float* __restrict__ rew, const float* __restrict__ rW, const float* __restrict__ rb)
{
    const int b = blockIdx.x, tid = threadIdx.x;
    const float* row = cc + (size_t)b * S4;
    float partial = 0.f;
    for (int s = tid; s < Ssz; s += 256) {
        float ig = 1.f / (1.f + expf(-row[s]));
        float fg = 1.f / (1.f + expf(-row[Ssz + s]));
        float og = 1.f / (1.f + expf(-row[2*Ssz + s]));
        float gg = tanhf(row[3*Ssz + s]);
        float cv = fg * c[(size_t)b * Ssz + s] + ig * gg;
        float hv = og * tanhf(cv);
        c[(size_t)b * Ssz + s] = cv;
        preds[(size_t)b * Ssz + s] = hv;
        __nv_bfloat16 h, l; split_bf(hv, h, l);
        size_t o = (size_t)b * K3S;
        hn3[o + s] = h; hn3[o + Ssz + s] = h; hn3[o + 2*Ssz + s] = l;
        partial += hv * rW[s];
    }
    __shared__ float red[256];
    red[tid] = partial; __syncthreads();
#pragma unroll
    for (int st = 128; st > 0; st >>= 1) {
        if (tid < st) red[tid] += red[tid + st];
        __syncthreads();
    }
    if (tid == 0) rew[b] = red[0] + rb[0];
}

extern "C" void kernel_launch(void* const* d_in, const int* in_sizes, int n_in,
                              void* d_out, int out_size)
{
    (void)in_sizes; (void)n_in; (void)out_size;
    const float* state = (const float*)d_in[0];
    const float* act   = (const float*)d_in[1];
    const float* lat   = (const float*)d_in[2];
    const float* fcW   = (const float*)d_in[3];
    const float* fcb   = (const float*)d_in[4];
    const float* fc1W  = (const float*)d_in[5];
    const float* fc2W  = (const float*)d_in[6];
    const float* WW    = (const float*)d_in[7];
    const float* rW    = (const float*)d_in[8];
    const float* rb    = (const float*)d_in[9];

    float* out   = (float*)d_out;
    float* preds = out;
    float* rews  = out + (size_t)Tt * Bsz * Ssz;

    __nv_bfloat16 *eff3, *fc23, *WW3, *fcs3, *fcap3, *al3, *st3, *h3, *x13, *x23, *hn3;
    float *base, *cc, *c;
    cudaGetSymbolAddress((void**)&eff3,  g_eff3);
    cudaGetSymbolAddress((void**)&fc23,  g_fc23);
    cudaGetSymbolAddress((void**)&WW3,   g_WW3);
    cudaGetSymbolAddress((void**)&fcs3,  g_fcs3);
    cudaGetSymbolAddress((void**)&fcap3, g_fcap3);
    cudaGetSymbolAddress((void**)&al3,   g_al3);
    cudaGetSymbolAddress((void**)&st3,   g_st3);
    cudaGetSymbolAddress((void**)&h3,    g_h3);
    cudaGetSymbolAddress((void**)&x13,   g_x13);
    cudaGetSymbolAddress((void**)&x23,   g_x23);
    cudaGetSymbolAddress((void**)&hn3,   g_hn3);
    cudaGetSymbolAddress((void**)&base,  g_base);
    cudaGetSymbolAddress((void**)&cc,    g_cc);
    cudaGetSymbolAddress((void**)&c,     g_c);

    cudaStream_t st = cudaStreamPerThread;
    const int TB = 256;
    {
        long n;
        n = (long)Ssz * Ssz;
        conveff_k<<<(int)((n + TB - 1) / TB), TB, 0, st>>>(fc1W, eff3);
        convw_k<<<(int)((n + TB - 1) / TB), TB, 0, st>>>(fc2W, Ssz, 0, Ssz, fc23, n);
        convw_k<<<(int)((n + TB - 1) / TB), TB, 0, st>>>(fcW, SAP, 0, Ssz, fcs3, n);
        n = (long)S4 * Ssz;
        convw_k<<<(int)((n + TB - 1) / TB), TB, 0, st>>>(WW, Ssz, 0, Ssz, WW3, n);
        n = (long)Ssz * KAP;
        convw_k<<<(int)((n + TB - 1) / TB), TB, 0, st>>>(fcW, SAP, Ssz, KAP, fcap3, n);
        n = (long)Bsz * Ssz;
        conva_k<<<(int)((n + TB - 1) / TB), TB, 0, st>>>(state, Ssz, Ssz, st3, n);
        n = (long)Tt * Bsz * KAP;
        packal_k<<<(int)((n + TB - 1) / TB), TB, 0, st>>>(act, lat, al3);
    }

    // base[t*B+b,:] = [act_t,lat] @ fcap^T + fcb  (fp32, no relu)
    mmagemm<3><<<dim3(Ssz/32, (Tt*Bsz)/128), 256, 0, st>>>(
        al3, K3P, fcap3, base, nullptr, fcb, Ssz, 0);

    // init: h = c = relu(state @ fcs^T + base[0])
    mmagemm<1><<<dim3(Ssz/32, Bsz/128), 256, 0, st>>>(
        st3, K3S, fcs3, c, h3, base, Ssz, Ssz);

    dim3 gm(Ssz/32, Bsz/128), g3(S4/32, Bsz/128);
    for (int t = 0; t < Tt; t++) {
        mmagemm<0><<<gm, 256, 0, st>>>(h3,  K3S, eff3, nullptr, x13, nullptr, Ssz, Ssz);
        mmagemm<0><<<gm, 256, 0, st>>>(x13, K3S, fc23, nullptr, x23, nullptr, Ssz, Ssz);
        mmagemm<2><<<g3, 256, 0, st>>>(x23, K3S, WW3, cc, nullptr, nullptr, S4, 0);
        gates_k<<<Bsz, 256, 0, st>>>(cc, c, hn3,
                                     preds + (size_t)t * Bsz * Ssz,
                                     rews + (size_t)t * Bsz, rW, rb);
        if (t < Tt - 1)
            mmagemm<1><<<gm, 256, 0, st>>>(hn3, K3S, fcs3, nullptr, h3,
                                           base + (size_t)t * Bsz * Ssz, Ssz, Ssz);
    }
}

// round 15
// speedup vs baseline: 1.4585x; 1.4585x over previous
#include <cuda_runtime.h>
#include <cuda_bf16.h>
#include <math.h>
#include <stdint.h>

#define Bsz 256
#define Tt  32
#define Ssz 2048
#define Asz 64
#define Psz 128
#define KAP 192
#define SAP 2240
#define S4  8192
#define K2S 4096          // 2*Ssz  (hi|lo rows)
#define K2P 384           // 2*KAP

// ---- scratch (device globals; allocation-free rule) ----
__device__ __nv_bfloat16 g_eff2 [(size_t)Ssz * K2S];
__device__ __nv_bfloat16 g_fc22 [(size_t)Ssz * K2S];
__device__ __nv_bfloat16 g_WW2  [(size_t)S4  * K2S];
__device__ __nv_bfloat16 g_fcs2 [(size_t)Ssz * K2S];
__device__ __nv_bfloat16 g_fcap2[(size_t)Ssz * K2P];
__device__ __nv_bfloat16 g_al2  [(size_t)Tt * Bsz * K2P];
__device__ __nv_bfloat16 g_st2  [(size_t)Bsz * K2S];
__device__ __nv_bfloat16 g_h2   [(size_t)Bsz * K2S];
__device__ __nv_bfloat16 g_x12  [(size_t)Bsz * K2S];
__device__ __nv_bfloat16 g_x22  [(size_t)Bsz * K2S];
__device__ __nv_bfloat16 g_hn2  [(size_t)Bsz * K2S];
__device__ float g_base[(size_t)Tt * Bsz * Ssz];
__device__ float g_cc  [(size_t)Bsz * S4];
__device__ float g_c   [(size_t)Bsz * Ssz];

__device__ __forceinline__ uint32_t smem_u32(const void* p) {
    uint32_t a;
    asm("{ .reg .u64 t; cvta.to.shared.u64 t, %1; cvt.u32.u64 %0, t; }" : "=r"(a) : "l"(p));
    return a;
}
__device__ __forceinline__ void ldmx4(uint32_t* r, uint32_t addr) {
    asm volatile("ldmatrix.sync.aligned.m8n8.x4.shared.b16 {%0,%1,%2,%3}, [%4];"
                 : "=r"(r[0]), "=r"(r[1]), "=r"(r[2]), "=r"(r[3]) : "r"(addr));
}
__device__ __forceinline__ void mma16816(float* c, const uint32_t* a, uint32_t b0, uint32_t b1) {
    asm volatile(
        "mma.sync.aligned.m16n8k16.row.col.f32.bf16.bf16.f32 "
        "{%0,%1,%2,%3}, {%4,%5,%6,%7}, {%8,%9}, {%0,%1,%2,%3};"
        : "+f"(c[0]), "+f"(c[1]), "+f"(c[2]), "+f"(c[3])
        : "r"(a[0]), "r"(a[1]), "r"(a[2]), "r"(a[3]), "r"(b0), "r"(b1));
}
#define CPA16(so, g) \
    asm volatile("cp.async.cg.shared.global [%0], [%1], 16;" :: "r"(so), "l"(g) : "memory")
#define CPCOMMIT() asm volatile("cp.async.commit_group;" ::: "memory")
#define CPWAIT1()  asm volatile("cp.async.wait_group 1;" ::: "memory")

// ---------------------------------------------------------------------------
// bf16 error-split GEMM: C = epi( Ah*Wh + Ah*Wl + Al*Wh ), fp32 acc.
// A2: [M, 2K] rows = [hi|lo]; W2: [N, 2K] rows = [hi|lo]. Three K-passes via
// per-stage segment offsets. CTA tile 128x64, BK=64, 8 warps (4Mx2N, 32x32),
// 3-stage cp.async pipeline. Stage smem: A 16KB + W 8KB = 24KB; total 72KB.
// MODE 0: relu -> O2 (bf16 hi|lo rows, length 2*Ssz)
// MODE 1: relu(acc + extra[m*Nfull+n]) -> O2 (+ optional fp32 dup to Cf)
// MODE 2: relu -> Cf fp32      MODE 3: acc + extra[n] -> Cf fp32 (no relu)
// ---------------------------------------------------------------------------
#define SMEMB 73728

template <int MODE>
__global__ __launch_bounds__(256, 2) void mmagemm(
    const __nv_bfloat16* __restrict__ A2, int K,
    const __nv_bfloat16* __restrict__ W2,
    float* __restrict__ Cf,
    __nv_bfloat16* __restrict__ O2,
    const float* __restrict__ extra,
    int Nfull)
{
    extern __shared__ char smem[];
    const uint32_t sbase = smem_u32(smem);
    const int tid = threadIdx.x, wid = tid >> 5, l = tid & 31;
    const int bm = blockIdx.y * 128, n0 = blockIdx.x * 64;
    const int mr = (wid >> 1) * 32, nb = (wid & 1) * 32;
    const int NSp = K >> 6, NS = NSp * 3;
    const int ldr = 2 * K;

    auto issue = [&](int s) {
        const int p = (s >= 2 * NSp) ? 2 : (s >= NSp ? 1 : 0);
        const int w = s - p * NSp;
        const int aoff = ((p == 2) ? K : 0) + w * 64;
        const int woff = ((p == 1) ? K : 0) + w * 64;
        const uint32_t sb = sbase + (uint32_t)(s % 3) * 24576u;
#pragma unroll
        for (int i = 0; i < 4; i++) {                  // A: 128 rows x 8 chunks
            const int id = tid + 256 * i, row = id >> 3, c = id & 7;
            const uint32_t so = sb + (uint32_t)(row * 128 + ((c * 16) ^ ((row & 7) << 4)));
            const __nv_bfloat16* g = A2 + (size_t)(bm + row) * ldr + aoff + c * 8;
            CPA16(so, g);
        }
#pragma unroll
        for (int i = 0; i < 2; i++) {                  // W: 64 rows x 8 chunks
            const int id = tid + 256 * i, row = id >> 3, c = id & 7;
            const uint32_t so = sb + 16384u + (uint32_t)(row * 128 + ((c * 16) ^ ((row & 7) << 4)));
            const __nv_bfloat16* g = W2 + (size_t)(n0 + row) * ldr + woff + c * 8;
            CPA16(so, g);
        }
    };

    float acc[2][4][4] = {};

    // ldmatrix per-lane address pieces
    const int rowA = mr + (l & 15);
    const uint32_t xra = (uint32_t)((rowA & 7) << 4);
    const uint32_t kh  = (uint32_t)((l >> 4) << 4);
    const int rowW = nb + (((l >> 4) & 1) << 3) + (l & 7);
    const uint32_t xrw = (uint32_t)((rowW & 7) << 4);
    const uint32_t wkh = (uint32_t)(((l >> 3) & 1) << 4);

    issue(0); CPCOMMIT();
    issue(1); CPCOMMIT();

    for (int s = 0; s < NS; s++) {
        CPWAIT1();
        __syncthreads();
        if (s + 2 < NS) issue(s + 2);
        CPCOMMIT();
        const uint32_t aB = sbase + (uint32_t)(s % 3) * 24576u;
        const uint32_t wB = aB + 16384u;
        const uint32_t a0r = aB + (uint32_t)(rowA * 128);
        const uint32_t a1r = a0r + 16u * 128u;
        const uint32_t w0r = wB + (uint32_t)(rowW * 128);
        const uint32_t w1r = w0r + 16u * 128u;
#pragma unroll
        for (int s4 = 0; s4 < 4; s4++) {
            uint32_t a0[4], a1[4], b0[4], b1[4];
            const uint32_t ca = kh + s4 * 32;
            const uint32_t cw = wkh + s4 * 32;
            ldmx4(a0, a0r + (ca ^ xra));
            ldmx4(a1, a1r + (ca ^ xra));
            ldmx4(b0, w0r + (cw ^ xrw));
            ldmx4(b1, w1r + (cw ^ xrw));
            mma16816(acc[0][0], a0, b0[0], b0[1]);
            mma16816(acc[0][1], a0, b0[2], b0[3]);
            mma16816(acc[0][2], a0, b1[0], b1[1]);
            mma16816(acc[0][3], a0, b1[2], b1[3]);
            mma16816(acc[1][0], a1, b0[0], b0[1]);
            mma16816(acc[1][1], a1, b0[2], b0[3]);
            mma16816(acc[1][2], a1, b1[0], b1[1]);
            mma16816(acc[1][3], a1, b1[2], b1[3]);
        }
        __syncthreads();
    }

    // ---- epilogue ----
#pragma unroll
    for (int g = 0; g < 2; g++) {
#pragma unroll
        for (int j = 0; j < 4; j++) {
            const int n = n0 + nb + j * 8 + (l & 3) * 2;
#pragma unroll
            for (int half = 0; half < 2; half++) {
                const int m = bm + mr + g * 16 + (l >> 2) + half * 8;
                float v0 = acc[g][j][half * 2 + 0];
                float v1 = acc[g][j][half * 2 + 1];
                if (MODE == 1) {
                    const float2 e = *(const float2*)(extra + (size_t)m * Nfull + n);
                    v0 += e.x; v1 += e.y;
                }
                if (MODE == 3) { v0 += extra[n]; v1 += extra[n + 1]; }
                if (MODE != 3) {
                    v0 = v0 > 0.f ? v0 : 0.f;
                    v1 = v1 > 0.f ? v1 : 0.f;
                }
                if (MODE >= 2 || (MODE == 1 && Cf != nullptr))
                    *(float2*)(Cf + (size_t)m * Nfull + n) = make_float2(v0, v1);
                if (MODE <= 1) {
                    __nv_bfloat16 h0 = __float2bfloat16_rn(v0);
                    __nv_bfloat16 h1 = __float2bfloat16_rn(v1);
                    __nv_bfloat16 l0 = __float2bfloat16_rn(v0 - __bfloat162float(h0));
                    __nv_bfloat16 l1 = __float2bfloat16_rn(v1 - __bfloat162float(h1));
                    uint32_t ph = ((uint32_t)__bfloat16_as_ushort(h1) << 16) | __bfloat16_as_ushort(h0);
                    uint32_t pl = ((uint32_t)__bfloat16_as_ushort(l1) << 16) | __bfloat16_as_ushort(l0);
                    __nv_bfloat16* ob = O2 + (size_t)m * K2S + n;
                    *(uint32_t*)(ob)       = ph;
                    *(uint32_t*)(ob + Ssz) = pl;
                }
            }
        }
    }
}

// ---- fused conversion: ONE launch builds every hi|lo operand ----
__global__ void conv_all(
    const float* __restrict__ state, const float* __restrict__ act,
    const float* __restrict__ lat, const float* __restrict__ fcW,
    const float* __restrict__ fc1W, const float* __restrict__ fc2W,
    const float* __restrict__ WW,
    __nv_bfloat16* __restrict__ eff2, __nv_bfloat16* __restrict__ fc22,
    __nv_bfloat16* __restrict__ fcs2, __nv_bfloat16* __restrict__ WW2,
    __nv_bfloat16* __restrict__ fcap2, __nv_bfloat16* __restrict__ st2,
    __nv_bfloat16* __restrict__ al2)
{
    const long E0 = (long)Ssz * Ssz;
    const long E1 = E0 + (long)Ssz * Ssz;
    const long E2 = E1 + (long)Ssz * Ssz;
    const long E3 = E2 + (long)S4 * Ssz;
    const long E4 = E3 + (long)Ssz * KAP;
    const long E5 = E4 + (long)Bsz * Ssz;
    const long E6 = E5 + (long)Tt * Bsz * KAP;
    long idx = (long)blockIdx.x * 256 + threadIdx.x;
    if (idx >= E6) return;
    float v; __nv_bfloat16* dst; long n; int k, Kb;
    if (idx < E0) {
        long t = idx; n = t / Ssz; k = (int)(t % Ssz); Kb = Ssz;
        v = fc1W[(size_t)n * 2 * Ssz + k] + fc1W[(size_t)n * 2 * Ssz + Ssz + k];
        dst = eff2;
    } else if (idx < E1) {
        long t = idx - E0; n = t / Ssz; k = (int)(t % Ssz); Kb = Ssz;
        v = fc2W[(size_t)n * Ssz + k]; dst = fc22;
    } else if (idx < E2) {
        long t = idx - E1; n = t / Ssz; k = (int)(t % Ssz); Kb = Ssz;
        v = fcW[(size_t)n * SAP + k]; dst = fcs2;
    } else if (idx < E3) {
        long t = idx - E2; n = t / Ssz; k = (int)(t % Ssz); Kb = Ssz;
        v = WW[(size_t)n * Ssz + k]; dst = WW2;
    } else if (idx < E4) {
        long t = idx - E3; n = t / KAP; k = (int)(t % KAP); Kb = KAP;
        v = fcW[(size_t)n * SAP + Ssz + k]; dst = fcap2;
    } else if (idx < E5) {
        long t = idx - E4; n = t / Ssz; k = (int)(t % Ssz); Kb = Ssz;
        v = state[(size_t)n * Ssz + k]; dst = st2;
    } else {
        long t = idx - E5; n = t / KAP; k = (int)(t % KAP); Kb = KAP;
        int b = (int)(n % Bsz), tt = (int)(n / Bsz);
        v = (k < Asz) ? act[((size_t)b * Tt + tt) * Asz + k]
                      : lat[(size_t)b * Psz + (k - Asz)];
        dst = al2;
    }
    __nv_bfloat16 h = __float2bfloat16_rn(v);
    __nv_bfloat16 lo = __float2bfloat16_rn(v - __bfloat162float(h));
    dst[(size_t)n * 2 * Kb + k]      = h;
    dst[(size_t)n * 2 * Kb + Kb + k] = lo;
}

// LSTM gates; emits hn as hi|lo bf16 rows for the carry GEMM.
__global__ __launch_bounds__(256) void gates_k(
    const float* __restrict__ cc, float* __restrict__ c,
    __nv_bfloat16* __restrict__ hn2, float* __restrict__ preds,
    float* __restrict__ rew, const float* __restrict__ rW, const float* __restrict__ rb)
{
    const int b = blockIdx.x, tid = threadIdx.x;
    const float* row = cc + (size_t)b * S4;
    float partial = 0.f;
    for (int s = tid; s < Ssz; s += 256) {
        float ig = 1.f / (1.f + expf(-row[s]));
        float fg = 1.f / (1.f + expf(-row[Ssz + s]));
        float og = 1.f / (1.f + expf(-row[2 * Ssz + s]));
        float gg = tanhf(row[3 * Ssz + s]);
        float cv = fg * c[(size_t)b * Ssz + s] + ig * gg;
        float hv = og * tanhf(cv);
        c[(size_t)b * Ssz + s] = cv;
        preds[(size_t)b * Ssz + s] = hv;
        __nv_bfloat16 h = __float2bfloat16_rn(hv);
        __nv_bfloat16 lo = __float2bfloat16_rn(hv - __bfloat162float(h));
        hn2[(size_t)b * K2S + s] = h;
        hn2[(size_t)b * K2S + Ssz + s] = lo;
        partial += hv * rW[s];
    }
    __shared__ float red[256];
    red[tid] = partial; __syncthreads();
#pragma unroll
    for (int st = 128; st > 0; st >>= 1) {
        if (tid < st) red[tid] += red[tid + st];
        __syncthreads();
    }
    if (tid == 0) rew[b] = red[0] + rb[0];
}

extern "C" void kernel_launch(void* const* d_in, const int* in_sizes, int n_in,
                              void* d_out, int out_size)
{
    (void)in_sizes; (void)n_in; (void)out_size;
    const float* state = (const float*)d_in[0];
    const float* act   = (const float*)d_in[1];
    const float* lat   = (const float*)d_in[2];
    const float* fcW   = (const float*)d_in[3];
    const float* fcb   = (const float*)d_in[4];
    const float* fc1W  = (const float*)d_in[5];
    const float* fc2W  = (const float*)d_in[6];
    const float* WW    = (const float*)d_in[7];
    const float* rW    = (const float*)d_in[8];
    const float* rb    = (const float*)d_in[9];

    float* out   = (float*)d_out;
    float* preds = out;
    float* rews  = out + (size_t)Tt * Bsz * Ssz;

    __nv_bfloat16 *eff2, *fc22, *WW2, *fcs2, *fcap2, *al2, *st2, *h2, *x12, *x22, *hn2;
    float *base, *cc, *c;
    cudaGetSymbolAddress((void**)&eff2,  g_eff2);
    cudaGetSymbolAddress((void**)&fc22,  g_fc22);
    cudaGetSymbolAddress((void**)&WW2,   g_WW2);
    cudaGetSymbolAddress((void**)&fcs2,  g_fcs2);
    cudaGetSymbolAddress((void**)&fcap2, g_fcap2);
    cudaGetSymbolAddress((void**)&al2,   g_al2);
    cudaGetSymbolAddress((void**)&st2,   g_st2);
    cudaGetSymbolAddress((void**)&h2,    g_h2);
    cudaGetSymbolAddress((void**)&x12,   g_x12);
    cudaGetSymbolAddress((void**)&x22,   g_x22);
    cudaGetSymbolAddress((void**)&hn2,   g_hn2);
    cudaGetSymbolAddress((void**)&base,  g_base);
    cudaGetSymbolAddress((void**)&cc,    g_cc);
    cudaGetSymbolAddress((void**)&c,     g_c);

    cudaFuncSetAttribute(mmagemm<0>, cudaFuncAttributeMaxDynamicSharedMemorySize, SMEMB);
    cudaFuncSetAttribute(mmagemm<1>, cudaFuncAttributeMaxDynamicSharedMemorySize, SMEMB);
    cudaFuncSetAttribute(mmagemm<2>, cudaFuncAttributeMaxDynamicSharedMemorySize, SMEMB);
    cudaFuncSetAttribute(mmagemm<3>, cudaFuncAttributeMaxDynamicSharedMemorySize, SMEMB);

    cudaStream_t st = cudaStreamPerThread;

    // launch 1: all conversions fused (so ncu -s5 -c1 lands on the cc GEMM)
    {
        long total = 3L * Ssz * Ssz + (long)S4 * Ssz + (long)Ssz * KAP
                   + (long)Bsz * Ssz + (long)Tt * Bsz * KAP;
        conv_all<<<(int)((total + 255) / 256), 256, 0, st>>>(
            state, act, lat, fcW, fc1W, fc2W, WW,
            eff2, fc22, fcs2, WW2, fcap2, st2, al2);
    }

    // launch 2: base[t*B+b,:] = [act_t,lat] @ fcap^T + fcb (fp32, no relu)
    mmagemm<3><<<dim3(Ssz / 64, (Tt * Bsz) / 128), 256, SMEMB, st>>>(
        al2, KAP, fcap2, base, nullptr, fcb, Ssz);

    // launch 3: init h = c = relu(state @ fcs^T + base[0])
    mmagemm<1><<<dim3(Ssz / 64, Bsz / 128), 256, SMEMB, st>>>(
        st2, Ssz, fcs2, c, h2, base, Ssz);

    dim3 gm(Ssz / 64, Bsz / 128), g3(S4 / 64, Bsz / 128);
    for (int t = 0; t < Tt; t++) {
        mmagemm<0><<<gm, 256, SMEMB, st>>>(h2,  Ssz, eff2, nullptr, x12, nullptr, Ssz);
        mmagemm<0><<<gm, 256, SMEMB, st>>>(x12, Ssz, fc22, nullptr, x22, nullptr, Ssz);
        mmagemm<2><<<g3, 256, SMEMB, st>>>(x22, Ssz, WW2, cc, nullptr, nullptr, S4);
        gates_k<<<Bsz, 256, 0, st>>>(cc, c, hn2,
                                     preds + (size_t)t * Bsz * Ssz,
                                     rews + (size_t)t * Bsz, rW, rb);
        if (t < Tt - 1)
            mmagemm<1><<<gm, 256, SMEMB, st>>>(hn2, Ssz, fcs2, nullptr, h2,
                                               base + (size_t)t * Bsz * Ssz, Ssz);
    }
}